// round 8
// baseline (speedup 1.0000x reference)
#include <cuda_runtime.h>
#include <cuda_fp16.h>
#include <cuda_bf16.h>
#include <cstdint>

// Problem: CrossBaby_1  (B=32, S=128, V=8192, E=256)
//   h    = relu(x @ w_emb^T + b_emb)                 [B*S, E]   <- HMMA fp16 2-pass
//   s    = sum_e h                                    [B, S]    <- fused into reduce1
//   Weff[b,e,j] = sum_k w_red[e, k*E+j] * s[b,k]      [B, E, E]
//   y    = relu(batched h_b @ Weff_b^T + b_red)       [B, S, E]
//   y2   = relu(y.flat @ w_red2^T + b_red2)           [B, E]
//   out  = y2 @ w_out^T + b_out                       [B, V]
//
// Target sm_100 (no 'a'): tensor path = mma.sync HMMA fp16.
// Stage-1: x = xh + xl (fp16 + unscaled fp16 residual, subnormals OK),
// w in fp16. Single fp32 accumulator: D = Ah*Bh + Al*Bh.

#define B_  32
#define S_  128
#define V_  8192
#define E_  256
#define M1_ (B_ * S_)
#define SPLITK 4

// ---------------- scratch (static device globals; no allocation) ------------
__device__ __align__(128) __half g_wh[E_ * V_];              // 4 MiB fp16 weights
__device__ __align__(128) float g_part1[SPLITK * M1_ * E_];  // 16 MiB
__device__ float g_h   [M1_ * E_];
__device__ float g_st  [S_ * B_];             // s transposed: [k][b]
__device__ float g_weff[B_ * E_ * E_];
__device__ float g_y   [M1_ * E_];
__device__ float g_part[128 * B_ * E_];
__device__ float g_y2  [B_ * E_];

// ---------------- PTX helpers ------------------------------------------------
__device__ __forceinline__ uint32_t smem_u32(const void* p) {
    uint32_t a;
    asm("{ .reg .u64 t; cvta.to.shared.u64 t, %1; cvt.u32.u64 %0, t; }" : "=r"(a) : "l"(p));
    return a;
}
__device__ __forceinline__ void cp16(uint32_t dst, const void* src) {
    asm volatile("cp.async.cg.shared.global [%0], [%1], 16;" :: "r"(dst), "l"(src) : "memory");
}
#define CP_COMMIT() asm volatile("cp.async.commit_group;" ::: "memory")
#define CP_WAIT(n)  asm volatile("cp.async.wait_group %0;" :: "n"(n) : "memory")

__device__ __forceinline__ void ldsm4(uint32_t* r, uint32_t addr) {
    asm volatile("ldmatrix.sync.aligned.m8n8.x4.shared.b16 {%0,%1,%2,%3}, [%4];"
        : "=r"(r[0]), "=r"(r[1]), "=r"(r[2]), "=r"(r[3]) : "r"(addr));
}
__device__ __forceinline__ void mma16816h(float* d, const uint32_t* a, uint32_t b0, uint32_t b1) {
    asm volatile("mma.sync.aligned.m16n8k16.row.col.f32.f16.f16.f32 "
        "{%0,%1,%2,%3}, {%4,%5,%6,%7}, {%8,%9}, {%0,%1,%2,%3};"
        : "+f"(d[0]), "+f"(d[1]), "+f"(d[2]), "+f"(d[3])
        : "r"(a[0]), "r"(a[1]), "r"(a[2]), "r"(a[3]), "r"(b0), "r"(b1));
}
__device__ __forceinline__ void sts128(uint32_t addr, uint32_t a, uint32_t b, uint32_t c, uint32_t d) {
    asm volatile("st.shared.v4.b32 [%0], {%1,%2,%3,%4};" :: "r"(addr), "r"(a), "r"(b), "r"(c), "r"(d) : "memory");
}

#define SW128(o) ((o) ^ (((o) >> 3) & 0x70))

// ============================================================================
// Stage-1 HMMA GEMM: part1[z][m][n] = sum_k x[m,k]*w_emb[n,k]
//   CTA 128x128, BK=64, 8 warps (warp 32x64), grid (32 m, 2 n, SPLITK z) = 256.
//   A: LDG.128 x8 regs (prefetched) -> in-reg fp16 hi/residual -> STS.
//   Single fp32 accumulator (residual unscaled); 2 CTAs/SM.
// ============================================================================
#define TK_     64
#define KSPAN   (V_ / SPLITK)       // 2048
#define NT_     (KSPAN / TK_)       // 32
#define AH_O    0
#define AL_O    16384
#define BH_O    32768
#define STG_SZ  49152               // Ah 16K + Al 16K + Bh 16K
#define SMEM_TOT (2 * STG_SZ)       // 98304

__global__ void __launch_bounds__(256, 2) gemm1_hmma_kernel(
    const float* __restrict__ x, const __half* __restrict__ wh,
    float* __restrict__ part1)
{
    extern __shared__ char smem[];
    const uint32_t sb = smem_u32(smem);
    const int tid = threadIdx.x;
    const int wid = tid >> 5;
    const int lane = tid & 31;

    const int m0 = blockIdx.x * 128;
    const int n0 = blockIdx.y * 128;
    const int z  = blockIdx.z;
    const int kbase = z * KSPAN;

    const int warp_m = wid & 3;
    const int warp_n = wid >> 2;

    float acc[2][8][4];
    #pragma unroll
    for (int mt = 0; mt < 2; mt++)
        #pragma unroll
        for (int q = 0; q < 8; q++)
            #pragma unroll
            for (int r = 0; r < 4; r++) acc[mt][q][r] = 0.f;

    // A prefetch: pair p = tid + i*256; row = p>>3, pch = p&7 (8x16B per 64-col row)
    float4 xa[8];
    auto prefetchA = [&](int k0) {
        #pragma unroll
        for (int i = 0; i < 4; i++) {
            const int p = tid + i * 256;
            const int row = p >> 3, pch = p & 7;
            const float4* g = (const float4*)(x + (size_t)(m0 + row) * V_ + k0) + pch * 2;
            xa[2 * i]     = g[0];
            xa[2 * i + 1] = g[1];
        }
    };
    // convert regs -> Ah (fp16) / Al (fp16 residual, unscaled) smem tiles
    auto convertA = [&](int s) {
        const uint32_t stg = sb + s * STG_SZ;
        #pragma unroll
        for (int i = 0; i < 4; i++) {
            const int p = tid + i * 256;
            const int row = p >> 3, pch = p & 7;
            const float f[8] = {xa[2*i].x, xa[2*i].y, xa[2*i].z, xa[2*i].w,
                                xa[2*i+1].x, xa[2*i+1].y, xa[2*i+1].z, xa[2*i+1].w};
            uint32_t hh[4], ll[4];
            #pragma unroll
            for (int q = 0; q < 4; q++) {
                __half2 H = __floats2half2_rn(f[2*q], f[2*q+1]);
                float r0 = f[2*q]   - __low2float(H);
                float r1 = f[2*q+1] - __high2float(H);
                __half2 L = __floats2half2_rn(r0, r1);
                hh[q] = *(uint32_t*)&H;
                ll[q] = *(uint32_t*)&L;
            }
            const uint32_t off = SW128((uint32_t)(row * 128 + pch * 16));
            sts128(stg + AH_O + off, hh[0], hh[1], hh[2], hh[3]);
            sts128(stg + AL_O + off, ll[0], ll[1], ll[2], ll[3]);
        }
    };
    // B fp16 via cp.async: 128 rows x 64 fp16
    auto issue_B = [&](int s, int k0) {
        const uint32_t stg = sb + s * STG_SZ + BH_O;
        #pragma unroll
        for (int i = 0; i < 4; i++) {
            const int c = tid + i * 256;
            const int row = c >> 3, ch = c & 7;
            cp16(stg + SW128((uint32_t)(row * 128 + ch * 16)),
                 wh + (size_t)(n0 + row) * V_ + k0 + ch * 8);
        }
    };

    const int rowsel = lane & 15;
    const int khalf  = lane >> 4;

    prefetchA(kbase);
    issue_B(0, kbase);
    CP_COMMIT();

    for (int t = 0; t < NT_; t++) {
        const int s = t & 1;
        convertA(s);                // A regs are scoreboarded; no cp.async wait needed
        CP_WAIT(0);                 // B(t) landed
        __syncthreads();            // STS visible; all warps past compute(t-1)
        if (t + 1 < NT_) {
            prefetchA(kbase + (t + 1) * TK_);
            issue_B(s ^ 1, kbase + (t + 1) * TK_);
            CP_COMMIT();
        }

        const uint32_t stg = sb + s * STG_SZ;
        #pragma unroll
        for (int k16 = 0; k16 < 4; k16++) {
            const uint32_t kb = (uint32_t)(k16 * 32 + khalf * 16);
            uint32_t ah[2][4], al[2][4], bh[4][4];
            #pragma unroll
            for (int mt = 0; mt < 2; mt++) {
                const uint32_t sw = SW128((uint32_t)((warp_m * 32 + mt * 16 + rowsel) * 128) + kb);
                ldsm4(ah[mt], stg + AH_O + sw);
                ldsm4(al[mt], stg + AL_O + sw);
            }
            #pragma unroll
            for (int nt = 0; nt < 4; nt++) {
                const uint32_t sw = SW128((uint32_t)((warp_n * 64 + nt * 16 + rowsel) * 128) + kb);
                ldsm4(bh[nt], stg + BH_O + sw);
            }
            #pragma unroll
            for (int mt = 0; mt < 2; mt++) {
                #pragma unroll
                for (int q = 0; q < 8; q++) {
                    const int nt = q >> 1, w = q & 1;
                    const uint32_t b0 = bh[nt][w], b1 = bh[nt][w + 2];
                    mma16816h(acc[mt][q], ah[mt], b0, b1);
                    mma16816h(acc[mt][q], al[mt], b0, b1);
                }
            }
        }
    }

    // ---- epilogue ----
    const int gid = lane >> 2;
    const int tig = lane & 3;
    float* base = part1 + (size_t)z * (M1_ * E_);
    #pragma unroll
    for (int mt = 0; mt < 2; mt++) {
        const int row0 = m0 + warp_m * 32 + mt * 16 + gid;
        #pragma unroll
        for (int q = 0; q < 8; q++) {
            const int col = n0 + warp_n * 64 + q * 8 + tig * 2;
            *(float2*)(base + (size_t)row0 * E_ + col)       = make_float2(acc[mt][q][0], acc[mt][q][1]);
            *(float2*)(base + (size_t)(row0 + 8) * E_ + col) = make_float2(acc[mt][q][2], acc[mt][q][3]);
        }
    }
}

// ---------------- convert w_emb fp32 -> fp16 ---------------------------------
__global__ void wconv_kernel(const float* __restrict__ in, __half* __restrict__ o, int n8)
{
    int i = blockIdx.x * blockDim.x + threadIdx.x;
    if (i >= n8) return;
    const float4* p = (const float4*)in;
    float4 a = p[2 * i], b = p[2 * i + 1];
    float v[8] = {a.x, a.y, a.z, a.w, b.x, b.y, b.z, b.w};
    union { __half e[8]; uint4 u; } H;
    #pragma unroll
    for (int q = 0; q < 8; q++) H.e[q] = __float2half_rn(v[q]);
    ((uint4*)o)[i] = H.u;
}

// ---------------- split-K reduce (4 ch) + bias + relu + rowsum ---------------
__global__ void reduce1_kernel(const float* __restrict__ part,
                               const float* __restrict__ b_emb,
                               float* __restrict__ h, float* __restrict__ st)
{
    const int warp = (blockIdx.x * blockDim.x + threadIdx.x) >> 5;   // row 0..4095
    const int lane = threadIdx.x & 31;
    const size_t CH = (size_t)M1_ * E_;
    const float* p0 = part + (size_t)warp * E_;
    float sum = 0.f;
    #pragma unroll
    for (int i = 0; i < 8; i++) {
        const int col = lane + i * 32;
        float v = p0[col] + p0[CH + col] + p0[2 * CH + col] + p0[3 * CH + col] + b_emb[col];
        v = fmaxf(v, 0.f);
        h[(size_t)warp * E_ + col] = v;
        sum += v;
    }
    #pragma unroll
    for (int o = 16; o > 0; o >>= 1) sum += __shfl_xor_sync(0xFFFFFFFFu, sum, o);
    if (lane == 0) {
        const int b = warp >> 7;
        const int k = warp & (S_ - 1);
        st[k * B_ + b] = sum;
    }
}

// ---------------- generic fp32 NT GEMM (stages 4, 5a, 6) ---------------------
template<int BM, int BN, int BK, int TM, int TN>
__global__ void gemm_nt_kernel(const float* __restrict__ A, int lda, long sAz,
                               const float* __restrict__ B, int ldb, long sBz,
                               float* __restrict__ C, int ldc, long sCz,
                               const float* __restrict__ bias,
                               int K, int do_relu)
{
    constexpr int THREADS = (BM * BN) / (TM * TN);
    constexpr int LA = (BM * BK) / THREADS;
    constexpr int LB = (BN * BK) / THREADS;
    constexpr int TX = BN / TN;

    __shared__ float As[BK][BM + 4];
    __shared__ float Bs[BK][BN + 4];

    const long z = blockIdx.z;
    A += z * sAz;  B += z * sBz;  C += z * sCz;

    const int m0 = blockIdx.x * BM;
    const int n0 = blockIdx.y * BN;
    const int tid = threadIdx.x;
    const int tx = tid % TX;
    const int ty = tid / TX;

    float acc[TM][TN];
    #pragma unroll
    for (int i = 0; i < TM; i++)
        #pragma unroll
        for (int j = 0; j < TN; j++) acc[i][j] = 0.f;

    float ra[LA], rb[LB];
    const int nTiles = K / BK;

    #pragma unroll
    for (int u = 0; u < LA; u++) {
        int idx = tid + u * THREADS;
        ra[u] = A[(long)(m0 + idx / BK) * lda + (idx % BK)];
    }
    #pragma unroll
    for (int u = 0; u < LB; u++) {
        int idx = tid + u * THREADS;
        rb[u] = B[(long)(n0 + idx / BK) * ldb + (idx % BK)];
    }
    #pragma unroll
    for (int u = 0; u < LA; u++) {
        int idx = tid + u * THREADS;
        As[idx % BK][idx / BK] = ra[u];
    }
    #pragma unroll
    for (int u = 0; u < LB; u++) {
        int idx = tid + u * THREADS;
        Bs[idx % BK][idx / BK] = rb[u];
    }
    __syncthreads();

    for (int t = 0; t < nTiles; t++) {
        const int k_next = (t + 1) * BK;
        const bool have_next = (t + 1) < nTiles;
        if (have_next) {
            #pragma unroll
            for (int u = 0; u < LA; u++) {
                int idx = tid + u * THREADS;
                ra[u] = A[(long)(m0 + idx / BK) * lda + k_next + (idx % BK)];
            }
            #pragma unroll
            for (int u = 0; u < LB; u++) {
                int idx = tid + u * THREADS;
                rb[u] = B[(long)(n0 + idx / BK) * ldb + k_next + (idx % BK)];
            }
        }

        #pragma unroll
        for (int kk = 0; kk < BK; kk++) {
            float a[TM], b[TN];
            #pragma unroll
            for (int i = 0; i < TM; i++) a[i] = As[kk][ty * TM + i];
            #pragma unroll
            for (int j = 0; j < TN; j++) b[j] = Bs[kk][tx * TN + j];
            #pragma unroll
            for (int i = 0; i < TM; i++)
                #pragma unroll
                for (int j = 0; j < TN; j++)
                    acc[i][j] = fmaf(a[i], b[j], acc[i][j]);
        }
        __syncthreads();

        if (have_next) {
            #pragma unroll
            for (int u = 0; u < LA; u++) {
                int idx = tid + u * THREADS;
                As[idx % BK][idx / BK] = ra[u];
            }
            #pragma unroll
            for (int u = 0; u < LB; u++) {
                int idx = tid + u * THREADS;
                Bs[idx % BK][idx / BK] = rb[u];
            }
            __syncthreads();
        }
    }

    #pragma unroll
    for (int i = 0; i < TM; i++) {
        const int m = m0 + ty * TM + i;
        #pragma unroll
        for (int j = 0; j < TN; j++) {
            const int n = n0 + tx * TN + j;
            float v = acc[i][j];
            if (bias) v += bias[n];
            if (do_relu) v = fmaxf(v, 0.f);
            C[(long)m * ldc + n] = v;
        }
    }
}

// ---------------- Weff[b,e,j] = sum_k w_red[e, k*E+j] * s[b,k] ---------------
// grid (E, 4): block handles 8 b's -> 1024 CTAs (fixes grid-limited occupancy).
// w_red hits DRAM once; 3 extra reads served by L2.
__global__ void weff_kernel(const float* __restrict__ w_red,
                            const float* __restrict__ st,
                            float* __restrict__ weff)
{
    __shared__ float s_sm[S_][8];
    const int e  = blockIdx.x;
    const int bq = blockIdx.y;           // b-quarter: rows bq*8 .. bq*8+7
    const int j  = threadIdx.x;

    for (int idx = threadIdx.x; idx < S_ * 8; idx += blockDim.x) {
        const int k = idx >> 3, b = idx & 7;
        s_sm[k][b] = st[k * B_ + bq * 8 + b];
    }
    __syncthreads();

    float acc[8];
    #pragma unroll
    for (int b = 0; b < 8; b++) acc[b] = 0.f;

    const float* wp = w_red + (long)e * (S_ * E_) + j;
    for (int k0 = 0; k0 < S_; k0 += 8) {
        float wv[8];
        #pragma unroll
        for (int u = 0; u < 8; u++)
            wv[u] = wp[(k0 + u) * E_];
        #pragma unroll
        for (int u = 0; u < 8; u++) {
            const float4 s0 = *(const float4*)&s_sm[k0 + u][0];
            const float4 s1 = *(const float4*)&s_sm[k0 + u][4];
            acc[0] = fmaf(wv[u], s0.x, acc[0]);
            acc[1] = fmaf(wv[u], s0.y, acc[1]);
            acc[2] = fmaf(wv[u], s0.z, acc[2]);
            acc[3] = fmaf(wv[u], s0.w, acc[3]);
            acc[4] = fmaf(wv[u], s1.x, acc[4]);
            acc[5] = fmaf(wv[u], s1.y, acc[5]);
            acc[6] = fmaf(wv[u], s1.z, acc[6]);
            acc[7] = fmaf(wv[u], s1.w, acc[7]);
        }
    }
    #pragma unroll
    for (int b = 0; b < 8; b++)
        weff[(long)(bq * 8 + b) * (E_ * E_) + e * E_ + j] = acc[b];
}

// ---------------- y2 split-K reduce + bias + relu ----------------------------
__global__ void reduce5_kernel(const float* __restrict__ part,
                               const float* __restrict__ b_red2,
                               float* __restrict__ y2)
{
    const int idx = blockIdx.x * blockDim.x + threadIdx.x;
    float v = 0.f;
    #pragma unroll 8
    for (int z = 0; z < 128; z++) v += part[z * (B_ * E_) + idx];
    v += b_red2[idx & (E_ - 1)];
    y2[idx] = fmaxf(v, 0.f);
}

// ---------------- launch -----------------------------------------------------
extern "C" void kernel_launch(void* const* d_in, const int* in_sizes, int n_in,
                              void* d_out, int out_size)
{
    const float* x      = (const float*)d_in[0];
    const float* w_emb  = (const float*)d_in[1];
    const float* b_emb  = (const float*)d_in[2];
    const float* w_red  = (const float*)d_in[3];
    const float* b_red  = (const float*)d_in[4];
    const float* w_red2 = (const float*)d_in[5];
    const float* b_red2 = (const float*)d_in[6];
    const float* w_out  = (const float*)d_in[7];
    const float* b_out  = (const float*)d_in[8];
    float* out = (float*)d_out;

    __half *wh_p;
    float *part1_p, *h_p, *st_p, *weff_p, *y_p, *part_p, *y2_p;
    cudaGetSymbolAddress((void**)&wh_p,    g_wh);
    cudaGetSymbolAddress((void**)&part1_p, g_part1);
    cudaGetSymbolAddress((void**)&h_p,     g_h);
    cudaGetSymbolAddress((void**)&st_p,    g_st);
    cudaGetSymbolAddress((void**)&weff_p,  g_weff);
    cudaGetSymbolAddress((void**)&y_p,     g_y);
    cudaGetSymbolAddress((void**)&part_p,  g_part);
    cudaGetSymbolAddress((void**)&y2_p,    g_y2);

    cudaFuncSetAttribute(gemm1_hmma_kernel,
                         cudaFuncAttributeMaxDynamicSharedMemorySize, SMEM_TOT);

    // Stage 1a: w_emb -> fp16
    wconv_kernel<<<(E_ * V_ / 8 + 255) / 256, 256>>>(w_emb, wh_p, E_ * V_ / 8);

    // Stage 1b: HMMA fp16 GEMM (register-staged split, merged acc) -> partials
    gemm1_hmma_kernel<<<dim3(M1_ / 128, E_ / 128, SPLITK), 256, SMEM_TOT>>>(
        x, wh_p, part1_p);

    // Stage 1c/2: reduce 4 partial channels + bias + relu -> h ; rowsum -> st
    reduce1_kernel<<<M1_ / 8, 256>>>(part1_p, b_emb, h_p, st_p);

    // Stage 3: Weff (b-split grid)
    weff_kernel<<<dim3(E_, 4), 256>>>(w_red, st_p, weff_p);

    // Stage 4: y = relu(batched h_b @ Weff_b^T + b_red)
    gemm_nt_kernel<128, 64, 16, 8, 4><<<dim3(1, 4, B_), 256>>>(
        h_p, E_, (long)S_ * E_,
        weff_p, E_, (long)E_ * E_,
        y_p, E_, (long)S_ * E_,
        b_red, E_, 1);

    // Stage 5a: y2 partials, split-K over K=32768 into 128 chunks of 256
    gemm_nt_kernel<32, 64, 16, 2, 4><<<dim3(1, 4, 128), 256>>>(
        y_p, S_ * E_, 256,
        w_red2, S_ * E_, 256,
        part_p, E_, (long)B_ * E_,
        nullptr, 256, 0);

    // Stage 5b: reduce + bias + relu
    reduce5_kernel<<<(B_ * E_) / 256, 256>>>(part_p, b_red2, y2_p);

    // Stage 6: out = y2 @ w_out^T + b_out
    gemm_nt_kernel<32, 64, 16, 2, 4><<<dim3(1, V_ / 64, 1), 256>>>(
        y2_p, E_, 0, w_out, E_, 0, out, V_, 0, b_out, E_, 0);
}

// round 11
// speedup vs baseline: 1.4683x; 1.4683x over previous
#include <cuda_runtime.h>
#include <cuda_fp16.h>
#include <cuda_bf16.h>
#include <cstdint>

// Problem: CrossBaby_1  (B=32, S=128, V=8192, E=256)
//   h    = relu(x @ w_emb^T + b_emb)                 [B*S, E]   <- HMMA fp16 1-pass
//   s    = sum_e h                                    [B, S]    <- fused into reduce1
//   Weff[b,e,j] = sum_k w_red[e, k*E+j] * s[b,k]      [B, E, E]
//   y    = relu(batched h_b @ Weff_b^T + b_red)       [B, S, E]
//   y2   = relu(y.flat @ w_red2^T + b_red2)           [B, E]
//   out  = y2 @ w_out^T + b_out                       [B, V]
//
// Target sm_100 (no 'a'): tensor path = mma.sync HMMA fp16.
// Stage-1 numerics: both x and w rounded to fp16 (single MMA pass).
// Measured calibration: w-only rounding -> rel_err 2.37e-4; adding x rounding
// predicts ~3.4e-4 (independent, same magnitude). 3x margin under 1e-3 gate.

#define B_  32
#define S_  128
#define V_  8192
#define E_  256
#define M1_ (B_ * S_)
#define SPLITK 2

// ---------------- scratch (static device globals; no allocation) ------------
__device__ __align__(128) __half g_wh[E_ * V_];              // 4 MiB fp16 weights
__device__ __align__(128) float g_part1[SPLITK * M1_ * E_];  // 8 MiB
__device__ float g_h   [M1_ * E_];
__device__ float g_st  [S_ * B_];             // s transposed: [k][b]
__device__ float g_weff[B_ * E_ * E_];
__device__ float g_y   [M1_ * E_];
__device__ float g_part[128 * B_ * E_];
__device__ float g_y2  [B_ * E_];

// ---------------- PTX helpers ------------------------------------------------
__device__ __forceinline__ uint32_t smem_u32(const void* p) {
    uint32_t a;
    asm("{ .reg .u64 t; cvta.to.shared.u64 t, %1; cvt.u32.u64 %0, t; }" : "=r"(a) : "l"(p));
    return a;
}
__device__ __forceinline__ void cp16(uint32_t dst, const void* src) {
    asm volatile("cp.async.cg.shared.global [%0], [%1], 16;" :: "r"(dst), "l"(src) : "memory");
}
#define CP_COMMIT() asm volatile("cp.async.commit_group;" ::: "memory")
#define CP_WAIT(n)  asm volatile("cp.async.wait_group %0;" :: "n"(n) : "memory")

__device__ __forceinline__ void ldsm4(uint32_t* r, uint32_t addr) {
    asm volatile("ldmatrix.sync.aligned.m8n8.x4.shared.b16 {%0,%1,%2,%3}, [%4];"
        : "=r"(r[0]), "=r"(r[1]), "=r"(r[2]), "=r"(r[3]) : "r"(addr));
}
__device__ __forceinline__ void mma16816h(float* d, const uint32_t* a, uint32_t b0, uint32_t b1) {
    asm volatile("mma.sync.aligned.m16n8k16.row.col.f32.f16.f16.f32 "
        "{%0,%1,%2,%3}, {%4,%5,%6,%7}, {%8,%9}, {%0,%1,%2,%3};"
        : "+f"(d[0]), "+f"(d[1]), "+f"(d[2]), "+f"(d[3])
        : "r"(a[0]), "r"(a[1]), "r"(a[2]), "r"(a[3]), "r"(b0), "r"(b1));
}
__device__ __forceinline__ void sts128(uint32_t addr, uint32_t a, uint32_t b, uint32_t c, uint32_t d) {
    asm volatile("st.shared.v4.b32 [%0], {%1,%2,%3,%4};" :: "r"(addr), "r"(a), "r"(b), "r"(c), "r"(d) : "memory");
}

#define SW128(o) ((o) ^ (((o) >> 3) & 0x70))

// ============================================================================
// Stage-1 HMMA GEMM: part1[z][m][n] = sum_k x[m,k]*w_emb[n,k]
//   CTA 128x128, BK=64, 8 warps (warp 32x64), grid (32 m, 2 n, 2 z) = 128.
//   A: LDG.128 x8 regs (prefetched) -> in-reg fp16 convert -> STS. 1-pass MMA.
// ============================================================================
#define TK_     64
#define KSPAN   (V_ / SPLITK)       // 4096
#define NT_     (KSPAN / TK_)       // 64
#define AH_O    0
#define BH_O    16384
#define STG_SZ  32768               // Ah 16K + Bh 16K
#define SMEM_TOT (2 * STG_SZ)       // 65536

__global__ void __launch_bounds__(256, 1) gemm1_hmma_kernel(
    const float* __restrict__ x, const __half* __restrict__ wh,
    float* __restrict__ part1)
{
    extern __shared__ char smem[];
    const uint32_t sb = smem_u32(smem);
    const int tid = threadIdx.x;
    const int wid = tid >> 5;
    const int lane = tid & 31;

    const int m0 = blockIdx.x * 128;
    const int n0 = blockIdx.y * 128;
    const int z  = blockIdx.z;
    const int kbase = z * KSPAN;

    const int warp_m = wid & 3;
    const int warp_n = wid >> 2;

    float acc[2][8][4];
    #pragma unroll
    for (int mt = 0; mt < 2; mt++)
        #pragma unroll
        for (int q = 0; q < 8; q++)
            #pragma unroll
            for (int r = 0; r < 4; r++) acc[mt][q][r] = 0.f;

    // A prefetch: pair p = tid + i*256; row = p>>3, pch = p&7 (8x16B per 64-col row)
    float4 xa[8];
    auto prefetchA = [&](int k0) {
        #pragma unroll
        for (int i = 0; i < 4; i++) {
            const int p = tid + i * 256;
            const int row = p >> 3, pch = p & 7;
            const float4* g = (const float4*)(x + (size_t)(m0 + row) * V_ + k0) + pch * 2;
            xa[2 * i]     = g[0];
            xa[2 * i + 1] = g[1];
        }
    };
    // convert regs -> Ah fp16 smem tile
    auto convertA = [&](int s) {
        const uint32_t stg = sb + s * STG_SZ;
        #pragma unroll
        for (int i = 0; i < 4; i++) {
            const int p = tid + i * 256;
            const int row = p >> 3, pch = p & 7;
            uint32_t hh[4];
            {
                __half2 h0 = __floats2half2_rn(xa[2*i].x, xa[2*i].y);
                __half2 h1 = __floats2half2_rn(xa[2*i].z, xa[2*i].w);
                __half2 h2 = __floats2half2_rn(xa[2*i+1].x, xa[2*i+1].y);
                __half2 h3 = __floats2half2_rn(xa[2*i+1].z, xa[2*i+1].w);
                hh[0] = *(uint32_t*)&h0; hh[1] = *(uint32_t*)&h1;
                hh[2] = *(uint32_t*)&h2; hh[3] = *(uint32_t*)&h3;
            }
            const uint32_t off = SW128((uint32_t)(row * 128 + pch * 16));
            sts128(stg + AH_O + off, hh[0], hh[1], hh[2], hh[3]);
        }
    };
    // B fp16 via cp.async: 128 rows x 64 fp16
    auto issue_B = [&](int s, int k0) {
        const uint32_t stg = sb + s * STG_SZ + BH_O;
        #pragma unroll
        for (int i = 0; i < 4; i++) {
            const int c = tid + i * 256;
            const int row = c >> 3, ch = c & 7;
            cp16(stg + SW128((uint32_t)(row * 128 + ch * 16)),
                 wh + (size_t)(n0 + row) * V_ + k0 + ch * 8);
        }
    };

    const int rowsel = lane & 15;
    const int khalf  = lane >> 4;

    prefetchA(kbase);
    issue_B(0, kbase);
    CP_COMMIT();

    for (int t = 0; t < NT_; t++) {
        const int s = t & 1;
        convertA(s);                // A regs scoreboarded; no cp.async wait needed
        CP_WAIT(0);                 // B(t) landed
        __syncthreads();            // STS visible; all warps past compute(t-1)
        if (t + 1 < NT_) {
            prefetchA(kbase + (t + 1) * TK_);
            issue_B(s ^ 1, kbase + (t + 1) * TK_);
            CP_COMMIT();
        }

        const uint32_t stg = sb + s * STG_SZ;
        #pragma unroll
        for (int k16 = 0; k16 < 4; k16++) {
            const uint32_t kb = (uint32_t)(k16 * 32 + khalf * 16);
            uint32_t ah[2][4], bh[4][4];
            #pragma unroll
            for (int mt = 0; mt < 2; mt++) {
                const uint32_t sw = SW128((uint32_t)((warp_m * 32 + mt * 16 + rowsel) * 128) + kb);
                ldsm4(ah[mt], stg + AH_O + sw);
            }
            #pragma unroll
            for (int nt = 0; nt < 4; nt++) {
                const uint32_t sw = SW128((uint32_t)((warp_n * 64 + nt * 16 + rowsel) * 128) + kb);
                ldsm4(bh[nt], stg + BH_O + sw);
            }
            #pragma unroll
            for (int mt = 0; mt < 2; mt++) {
                #pragma unroll
                for (int q = 0; q < 8; q++) {
                    const int nt = q >> 1, w = q & 1;
                    mma16816h(acc[mt][q], ah[mt], bh[nt][w], bh[nt][w + 2]);
                }
            }
        }
    }

    // ---- epilogue ----
    const int gid = lane >> 2;
    const int tig = lane & 3;
    float* base = part1 + (size_t)z * (M1_ * E_);
    #pragma unroll
    for (int mt = 0; mt < 2; mt++) {
        const int row0 = m0 + warp_m * 32 + mt * 16 + gid;
        #pragma unroll
        for (int q = 0; q < 8; q++) {
            const int col = n0 + warp_n * 64 + q * 8 + tig * 2;
            *(float2*)(base + (size_t)row0 * E_ + col)       = make_float2(acc[mt][q][0], acc[mt][q][1]);
            *(float2*)(base + (size_t)(row0 + 8) * E_ + col) = make_float2(acc[mt][q][2], acc[mt][q][3]);
        }
    }
}

// ---------------- convert w_emb fp32 -> fp16 ---------------------------------
__global__ void wconv_kernel(const float* __restrict__ in, __half* __restrict__ o, int n8)
{
    int i = blockIdx.x * blockDim.x + threadIdx.x;
    if (i >= n8) return;
    const float4* p = (const float4*)in;
    float4 a = p[2 * i], b = p[2 * i + 1];
    float v[8] = {a.x, a.y, a.z, a.w, b.x, b.y, b.z, b.w};
    union { __half e[8]; uint4 u; } H;
    #pragma unroll
    for (int q = 0; q < 8; q++) H.e[q] = __float2half_rn(v[q]);
    ((uint4*)o)[i] = H.u;
}

// ---------------- split-K reduce (2 ch) + bias + relu + rowsum ---------------
__global__ void reduce1_kernel(const float* __restrict__ part,
                               const float* __restrict__ b_emb,
                               float* __restrict__ h, float* __restrict__ st)
{
    const int warp = (blockIdx.x * blockDim.x + threadIdx.x) >> 5;   // row 0..4095
    const int lane = threadIdx.x & 31;
    const size_t CH = (size_t)M1_ * E_;
    const float* p0 = part + (size_t)warp * E_;
    float sum = 0.f;
    #pragma unroll
    for (int i = 0; i < 8; i++) {
        const int col = lane + i * 32;
        float v = p0[col] + p0[CH + col] + b_emb[col];
        v = fmaxf(v, 0.f);
        h[(size_t)warp * E_ + col] = v;
        sum += v;
    }
    #pragma unroll
    for (int o = 16; o > 0; o >>= 1) sum += __shfl_xor_sync(0xFFFFFFFFu, sum, o);
    if (lane == 0) {
        const int b = warp >> 7;
        const int k = warp & (S_ - 1);
        st[k * B_ + b] = sum;
    }
}

// ---------------- generic fp32 NT GEMM (stages 4, 5a, 6) ---------------------
template<int BM, int BN, int BK, int TM, int TN>
__global__ void gemm_nt_kernel(const float* __restrict__ A, int lda, long sAz,
                               const float* __restrict__ B, int ldb, long sBz,
                               float* __restrict__ C, int ldc, long sCz,
                               const float* __restrict__ bias,
                               int K, int do_relu)
{
    constexpr int THREADS = (BM * BN) / (TM * TN);
    constexpr int LA = (BM * BK) / THREADS;
    constexpr int LB = (BN * BK) / THREADS;
    constexpr int TX = BN / TN;

    __shared__ float As[BK][BM + 4];
    __shared__ float Bs[BK][BN + 4];

    const long z = blockIdx.z;
    A += z * sAz;  B += z * sBz;  C += z * sCz;

    const int m0 = blockIdx.x * BM;
    const int n0 = blockIdx.y * BN;
    const int tid = threadIdx.x;
    const int tx = tid % TX;
    const int ty = tid / TX;

    float acc[TM][TN];
    #pragma unroll
    for (int i = 0; i < TM; i++)
        #pragma unroll
        for (int j = 0; j < TN; j++) acc[i][j] = 0.f;

    float ra[LA], rb[LB];
    const int nTiles = K / BK;

    #pragma unroll
    for (int u = 0; u < LA; u++) {
        int idx = tid + u * THREADS;
        ra[u] = A[(long)(m0 + idx / BK) * lda + (idx % BK)];
    }
    #pragma unroll
    for (int u = 0; u < LB; u++) {
        int idx = tid + u * THREADS;
        rb[u] = B[(long)(n0 + idx / BK) * ldb + (idx % BK)];
    }
    #pragma unroll
    for (int u = 0; u < LA; u++) {
        int idx = tid + u * THREADS;
        As[idx % BK][idx / BK] = ra[u];
    }
    #pragma unroll
    for (int u = 0; u < LB; u++) {
        int idx = tid + u * THREADS;
        Bs[idx % BK][idx / BK] = rb[u];
    }
    __syncthreads();

    for (int t = 0; t < nTiles; t++) {
        const int k_next = (t + 1) * BK;
        const bool have_next = (t + 1) < nTiles;
        if (have_next) {
            #pragma unroll
            for (int u = 0; u < LA; u++) {
                int idx = tid + u * THREADS;
                ra[u] = A[(long)(m0 + idx / BK) * lda + k_next + (idx % BK)];
            }
            #pragma unroll
            for (int u = 0; u < LB; u++) {
                int idx = tid + u * THREADS;
                rb[u] = B[(long)(n0 + idx / BK) * ldb + k_next + (idx % BK)];
            }
        }

        #pragma unroll
        for (int kk = 0; kk < BK; kk++) {
            float a[TM], b[TN];
            #pragma unroll
            for (int i = 0; i < TM; i++) a[i] = As[kk][ty * TM + i];
            #pragma unroll
            for (int j = 0; j < TN; j++) b[j] = Bs[kk][tx * TN + j];
            #pragma unroll
            for (int i = 0; i < TM; i++)
                #pragma unroll
                for (int j = 0; j < TN; j++)
                    acc[i][j] = fmaf(a[i], b[j], acc[i][j]);
        }
        __syncthreads();

        if (have_next) {
            #pragma unroll
            for (int u = 0; u < LA; u++) {
                int idx = tid + u * THREADS;
                As[idx % BK][idx / BK] = ra[u];
            }
            #pragma unroll
            for (int u = 0; u < LB; u++) {
                int idx = tid + u * THREADS;
                Bs[idx % BK][idx / BK] = rb[u];
            }
            __syncthreads();
        }
    }

    #pragma unroll
    for (int i = 0; i < TM; i++) {
        const int m = m0 + ty * TM + i;
        #pragma unroll
        for (int j = 0; j < TN; j++) {
            const int n = n0 + tx * TN + j;
            float v = acc[i][j];
            if (bias) v += bias[n];
            if (do_relu) v = fmaxf(v, 0.f);
            C[(long)m * ldc + n] = v;
        }
    }
}

// ---------------- Weff[b,e,j] = sum_k w_red[e, k*E+j] * s[b,k] ---------------
// round-6 version (best measured): one block per e, batched w loads (MLP=8)
__global__ void weff_kernel(const float* __restrict__ w_red,
                            const float* __restrict__ st,
                            float* __restrict__ weff)
{
    __shared__ float4 s_sm[S_ * (B_ / 4)];
    const int e = blockIdx.x;
    const int j = threadIdx.x;

    for (int idx = threadIdx.x; idx < S_ * B_; idx += blockDim.x)
        ((float*)s_sm)[idx] = st[idx];
    __syncthreads();

    float acc[B_];
    #pragma unroll
    for (int b = 0; b < B_; b++) acc[b] = 0.f;

    const float* wp = w_red + (long)e * (S_ * E_) + j;
    for (int k0 = 0; k0 < S_; k0 += 8) {
        float wv[8];
        #pragma unroll
        for (int u = 0; u < 8; u++)
            wv[u] = wp[(k0 + u) * E_];
        #pragma unroll
        for (int u = 0; u < 8; u++) {
            const float w = wv[u];
            #pragma unroll
            for (int bb = 0; bb < B_ / 4; bb++) {
                const float4 sv = s_sm[(k0 + u) * (B_ / 4) + bb];
                acc[bb * 4 + 0] = fmaf(w, sv.x, acc[bb * 4 + 0]);
                acc[bb * 4 + 1] = fmaf(w, sv.y, acc[bb * 4 + 1]);
                acc[bb * 4 + 2] = fmaf(w, sv.z, acc[bb * 4 + 2]);
                acc[bb * 4 + 3] = fmaf(w, sv.w, acc[bb * 4 + 3]);
            }
        }
    }
    #pragma unroll
    for (int b = 0; b < B_; b++)
        weff[(long)b * (E_ * E_) + e * E_ + j] = acc[b];
}

// ---------------- y2 split-K reduce + bias + relu ----------------------------
__global__ void reduce5_kernel(const float* __restrict__ part,
                               const float* __restrict__ b_red2,
                               float* __restrict__ y2)
{
    const int idx = blockIdx.x * blockDim.x + threadIdx.x;
    float v = 0.f;
    #pragma unroll 8
    for (int z = 0; z < 128; z++) v += part[z * (B_ * E_) + idx];
    v += b_red2[idx & (E_ - 1)];
    y2[idx] = fmaxf(v, 0.f);
}

// ---------------- launch -----------------------------------------------------
extern "C" void kernel_launch(void* const* d_in, const int* in_sizes, int n_in,
                              void* d_out, int out_size)
{
    const float* x      = (const float*)d_in[0];
    const float* w_emb  = (const float*)d_in[1];
    const float* b_emb  = (const float*)d_in[2];
    const float* w_red  = (const float*)d_in[3];
    const float* b_red  = (const float*)d_in[4];
    const float* w_red2 = (const float*)d_in[5];
    const float* b_red2 = (const float*)d_in[6];
    const float* w_out  = (const float*)d_in[7];
    const float* b_out  = (const float*)d_in[8];
    float* out = (float*)d_out;

    __half *wh_p;
    float *part1_p, *h_p, *st_p, *weff_p, *y_p, *part_p, *y2_p;
    cudaGetSymbolAddress((void**)&wh_p,    g_wh);
    cudaGetSymbolAddress((void**)&part1_p, g_part1);
    cudaGetSymbolAddress((void**)&h_p,     g_h);
    cudaGetSymbolAddress((void**)&st_p,    g_st);
    cudaGetSymbolAddress((void**)&weff_p,  g_weff);
    cudaGetSymbolAddress((void**)&y_p,     g_y);
    cudaGetSymbolAddress((void**)&part_p,  g_part);
    cudaGetSymbolAddress((void**)&y2_p,    g_y2);

    cudaFuncSetAttribute(gemm1_hmma_kernel,
                         cudaFuncAttributeMaxDynamicSharedMemorySize, SMEM_TOT);

    // Stage 1a: w_emb -> fp16
    wconv_kernel<<<(E_ * V_ / 8 + 255) / 256, 256>>>(w_emb, wh_p, E_ * V_ / 8);

    // Stage 1b: HMMA fp16 1-pass GEMM -> split-K partials
    gemm1_hmma_kernel<<<dim3(M1_ / 128, E_ / 128, SPLITK), 256, SMEM_TOT>>>(
        x, wh_p, part1_p);

    // Stage 1c/2: reduce 2 partial channels + bias + relu -> h ; rowsum -> st
    reduce1_kernel<<<M1_ / 8, 256>>>(part1_p, b_emb, h_p, st_p);

    // Stage 3: Weff
    weff_kernel<<<E_, 256>>>(w_red, st_p, weff_p);

    // Stage 4: y = relu(batched h_b @ Weff_b^T + b_red)
    gemm_nt_kernel<128, 64, 16, 8, 4><<<dim3(1, 4, B_), 256>>>(
        h_p, E_, (long)S_ * E_,
        weff_p, E_, (long)E_ * E_,
        y_p, E_, (long)S_ * E_,
        b_red, E_, 1);

    // Stage 5a: y2 partials, split-K over K=32768 into 128 chunks of 256
    gemm_nt_kernel<32, 64, 16, 2, 4><<<dim3(1, 4, 128), 256>>>(
        y_p, S_ * E_, 256,
        w_red2, S_ * E_, 256,
        part_p, E_, (long)B_ * E_,
        nullptr, 256, 0);

    // Stage 5b: reduce + bias + relu
    reduce5_kernel<<<(B_ * E_) / 256, 256>>>(part_p, b_red2, y2_p);

    // Stage 6: out = y2 @ w_out^T + b_out
    gemm_nt_kernel<32, 64, 16, 2, 4><<<dim3(1, V_ / 64, 1), 256>>>(
        y2_p, E_, 0, w_out, E_, 0, out, V_, 0, b_out, E_, 0);
}